// round 15
// baseline (speedup 1.0000x reference)
#include <cuda_runtime.h>
#include <cstdint>
#include <cstddef>

#define B_   32
#define T_   256
#define S_   256
#define H_   1024
#define IN3D 1536
#define LDIH 2560
#define AT_OFF 8388608u
#define CP_OFF 10485760u
#define GRID_SEQ 256

// scratch (static device globals; no allocation)
__device__ float g_X  [12582912];   // [8192][1536] row = t*32+b
__device__ float g_pre[33554432];   // [256][32][4096]
__device__ float g_Ka [8388608];    // [32][256][1024]
__device__ float g_Kc [8388608];
__device__ float g_buf[8421376];    // [32][257][1024]
__device__ float g_h  [65536];      // ping-pong [2][32][1024]
__device__ float g_c  [32768];
__device__ float g_cvec[32768];
__device__ float g_sc1[8192];
__device__ float g_sc2[8192];
__device__ unsigned g_barA = 0;
__device__ unsigned g_barGen = 0;

__device__ __forceinline__ float sigm(float x){ return 1.f/(1.f + __expf(-x)); }

// grid-wide barrier (all GRID_SEQ blocks resident; cg::grid_sync pattern)
__device__ __forceinline__ void gridbar()
{
    __syncthreads();
    if (threadIdx.x == 0) {
        volatile unsigned* vg = &g_barGen;
        unsigned gen = *vg;
        __threadfence();
        if (atomicAdd(&g_barA, 1u) == GRID_SEQ - 1u) {
            g_barA = 0u;
            __threadfence();
            *vg = gen + 1u;
        } else {
            while (*vg == gen) __nanosleep(64);
        }
        __threadfence();
    }
    __syncthreads();
}

// ---------------- pre-phase kernels ----------------
__global__ void k_gather(const int* __restrict__ nt, const int* __restrict__ pr,
                         const int* __restrict__ par,
                         const float* __restrict__ nt_emb,
                         const float* __restrict__ rule_emb)
{
    int row = blockIdx.x;            // t*32+b
    int t = row >> 5, b = row & 31;
    int tid = threadIdx.x;           // 128
    const float* s0 = nt_emb   + (size_t)nt [b * T_ + t] * 512;
    const float* s1 = rule_emb + (size_t)pr [b * T_ + t] * 512;
    const float* s2 = rule_emb + (size_t)par[b * T_ + t] * 512;
    float4* dst = (float4*)(g_X + (size_t)row * IN3D);
#pragma unroll
    for (int l = 0; l < 3; ++l) {
        int f = tid + 128 * l, seg = f >> 7, off = f & 127;
        const float* sp = (seg == 0) ? s0 : ((seg == 1) ? s1 : s2);
        dst[f] = ((const float4*)sp)[off];
    }
}

// C[m][n] = sum_k A[m][k] * (BT ? Bm[n][k] : Bm[k][n]) (+bias1[n]+bias2[n])
template<int BT>
__global__ __launch_bounds__(256) void sgemm128(
    const float* __restrict__ A, int lda,
    const float* __restrict__ Bm, int ldb,
    float* __restrict__ C, int ldc, int K,
    const float* __restrict__ bias1, const float* __restrict__ bias2)
{
    __shared__ __align__(16) float As[16][132];
    __shared__ __align__(16) float Bs[16][132];
    int tid = threadIdx.x;
    int m0 = blockIdx.y * 128, n0 = blockIdx.x * 128;
    int tm = tid >> 4, tn = tid & 15;
    float acc[8][8];
#pragma unroll
    for (int i = 0; i < 8; ++i)
#pragma unroll
        for (int j = 0; j < 8; ++j) acc[i][j] = 0.f;

    for (int kt = 0; kt < K; kt += 16) {
#pragma unroll
        for (int l = 0; l < 2; ++l) {
            int idx = tid + 256 * l, r = idx >> 2, kv = idx & 3;
            float4 v = *(const float4*)(A + (size_t)(m0 + r) * lda + kt + kv * 4);
            As[kv*4+0][r] = v.x; As[kv*4+1][r] = v.y;
            As[kv*4+2][r] = v.z; As[kv*4+3][r] = v.w;
        }
        if (BT) {
#pragma unroll
            for (int l = 0; l < 2; ++l) {
                int idx = tid + 256 * l, r = idx >> 2, kv = idx & 3;
                float4 v = *(const float4*)(Bm + (size_t)(n0 + r) * ldb + kt + kv * 4);
                Bs[kv*4+0][r] = v.x; Bs[kv*4+1][r] = v.y;
                Bs[kv*4+2][r] = v.z; Bs[kv*4+3][r] = v.w;
            }
        } else {
#pragma unroll
            for (int l = 0; l < 2; ++l) {
                int idx = tid + 256 * l, kr = idx >> 5, nv = idx & 31;
                *(float4*)&Bs[kr][nv * 4] =
                    *(const float4*)(Bm + (size_t)(kt + kr) * ldb + n0 + nv * 4);
            }
        }
        __syncthreads();
#pragma unroll
        for (int kk = 0; kk < 16; ++kk) {
            float4 a0 = *(float4*)&As[kk][tm * 8];
            float4 a1 = *(float4*)&As[kk][tm * 8 + 4];
            float4 b0 = *(float4*)&Bs[kk][tn * 8];
            float4 b1 = *(float4*)&Bs[kk][tn * 8 + 4];
            float av[8] = {a0.x,a0.y,a0.z,a0.w,a1.x,a1.y,a1.z,a1.w};
            float bv[8] = {b0.x,b0.y,b0.z,b0.w,b1.x,b1.y,b1.z,b1.w};
#pragma unroll
            for (int i = 0; i < 8; ++i)
#pragma unroll
                for (int j = 0; j < 8; ++j) acc[i][j] += av[i] * bv[j];
        }
        __syncthreads();
    }
#pragma unroll
    for (int i = 0; i < 8; ++i) {
        int m = m0 + tm * 8 + i;
#pragma unroll
        for (int j = 0; j < 8; ++j) {
            int n = n0 + tn * 8 + j;
            float v = acc[i][j];
            if (bias1) v += bias1[n] + bias2[n];
            C[(size_t)m * ldc + n] = v;
        }
    }
}

// ---------------- persistent sequential kernel phases ----------------

// P1: gates GEMM + LSTM + buf scatter. blocks 0..127 active; warp->j, lane->b.
__device__ __forceinline__ void phase_gates(
    float* sh, int* selS,
    const float* __restrict__ Whh, const float* __restrict__ Wih,
    const int* __restrict__ parent_t, int i,
    const float* __restrict__ hin, float* __restrict__ hout)
{
    if (blockIdx.x >= 128) return;
    float* xs = sh;             // [32][68]
    float* ws = sh + 2176;      // [32][68]
    int tid = threadIdx.x, warp = tid >> 5, lane = tid & 31;
    int j0 = blockIdx.x * 8;
    if (tid < 32) {
        int pidx = parent_t[tid * T_ + i];
        selS[tid] = (pidx < i) ? (pidx + 1) : 0;
    }
    __syncthreads();
    float a0 = 0.f, a1 = 0.f, a2 = 0.f, a3 = 0.f;

    for (int ph = 0; ph < 2; ++ph) {
        const float* Wb = (ph == 0) ? Whh : Wih;
        int ldw = (ph == 0) ? 1024 : LDIH;
        int coff = (ph == 0) ? 0 : IN3D;
        for (int kc = 0; kc < 1024; kc += 64) {
#pragma unroll
            for (int l = 0; l < 2; ++l) {
                int idx = tid + 256 * l, b = idx >> 4, k4 = idx & 15;
                const float* xp = (ph == 0)
                    ? (hin + b * H_)
                    : (g_buf + ((size_t)b * 257 + selS[b]) * 1024);
                *(float4*)&xs[b * 68 + k4 * 4] = *(const float4*)(xp + kc + k4 * 4);
            }
#pragma unroll
            for (int l = 0; l < 2; ++l) {
                int idx = tid + 256 * l, lr = idx >> 4, k4 = idx & 15;
                int grow = ((lr >> 3) << 10) + j0 + (lr & 7);
                *(float4*)&ws[lr * 68 + k4 * 4] =
                    *(const float4*)(Wb + (size_t)grow * ldw + coff + kc + k4 * 4);
            }
            __syncthreads();
#pragma unroll
            for (int kk = 0; kk < 16; ++kk) {
                float4 x  = *(float4*)&xs[lane * 68 + kk * 4];
                float4 w0 = *(float4*)&ws[warp * 68 + kk * 4];
                float4 w1 = *(float4*)&ws[(8 + warp) * 68 + kk * 4];
                float4 w2 = *(float4*)&ws[(16 + warp) * 68 + kk * 4];
                float4 w3 = *(float4*)&ws[(24 + warp) * 68 + kk * 4];
                a0 += w0.x*x.x + w0.y*x.y + w0.z*x.z + w0.w*x.w;
                a1 += w1.x*x.x + w1.y*x.y + w1.z*x.z + w1.w*x.w;
                a2 += w2.x*x.x + w2.y*x.y + w2.z*x.z + w2.w*x.w;
                a3 += w3.x*x.x + w3.y*x.y + w3.z*x.z + w3.w*x.w;
            }
            __syncthreads();
        }
    }
    int b = lane, j = j0 + warp;
    size_t pb = ((size_t)i * 32 + b) * 4096;
    float gi = a0 + g_pre[pb + j];
    float gf = a1 + g_pre[pb + 1024 + j];
    float gg = a2 + g_pre[pb + 2048 + j];
    float go = a3 + g_pre[pb + 3072 + j];
    float cn = sigm(gf) * g_c[b * H_ + j] + sigm(gi) * tanhf(gg);
    float hn = sigm(go) * tanhf(cn);
    g_c[b * H_ + j] = cn;
    hout[b * H_ + j] = hn;
    g_buf[((size_t)b * 257 + i + 1) * 1024 + j] = hn;
}

// P2: scores. 512 warp-group units on 256 blocks; q kept in registers (no smem).
// units 0..255: sc1 = h.Ka (step i); 256..511: sc2 = aout(i-1).Kc
__device__ __forceinline__ void phase_scores(
    const int* __restrict__ clen, const float* __restrict__ outbuf,
    const float* __restrict__ hcur, int i, int do1, int do2)
{
    int tid = threadIdx.x, warp = tid >> 5, lane = tid & 31;
    int unit = blockIdx.x * 2 + (warp >> 2);   // 0..511
    int second = (unit >= 256);
    if (second ? !do2 : !do1) return;
    int sub = unit & 255, b = sub >> 3, s0 = (sub & 7) * 32;
    int wIn = warp & 3;

    const float* q;  const float* Km;  float* outp;
    if (!second) { q = hcur + b * H_;                            Km = g_Ka; outp = g_sc1; }
    else         { q = outbuf + ((size_t)b * T_ + (i - 1)) * H_; Km = g_Kc; outp = g_sc2; }
    float4 qv[8];
#pragma unroll
    for (int u = 0; u < 8; ++u) qv[u] = *(const float4*)(q + lane * 4 + u * 128);
    int len = clen[b];
#pragma unroll
    for (int m = 0; m < 8; ++m) {
        int s = s0 + wIn * 8 + m;
        const float* kr = Km + ((size_t)b * S_ + s) * H_;
        float a = 0.f;
#pragma unroll
        for (int u = 0; u < 8; ++u) {
            float4 kv = *(const float4*)(kr + lane * 4 + u * 128);
            a += kv.x*qv[u].x + kv.y*qv[u].y + kv.z*qv[u].z + kv.w*qv[u].w;
        }
#pragma unroll
        for (int o = 16; o > 0; o >>= 1) a += __shfl_xor_sync(0xffffffffu, a, o);
        if (lane == 0) outp[b * S_ + s] = (s < len) ? a : -1e30f;
    }
}

// P3: softmax + cvec slices + score outputs.
// blocks 0..127: (b, hslice) from sc1; 128..159: sc2 -> copy_scores step i-1
__device__ __forceinline__ void phase_cvec(
    float* sh, const float* __restrict__ context, float* __restrict__ outbuf,
    int i, int doA, int doB)
{
    float* ps  = sh;        // [256]
    float* red = sh + 256;  // [256]
    int bid = blockIdx.x, tid = threadIdx.x;
    if (bid >= 160) return;
    int typeB = (bid >= 128);
    if (typeB ? !doB : !doA) return;
    int b, slice = 0;
    const float* sc;
    if (!typeB) { b = bid >> 2; slice = bid & 3; sc = g_sc1 + b * S_; }
    else        { b = bid - 128;                 sc = g_sc2 + b * S_; }

    float v = sc[tid];
    red[tid] = v; __syncthreads();
    for (int o = 128; o > 0; o >>= 1) { if (tid < o) red[tid] = fmaxf(red[tid], red[tid+o]); __syncthreads(); }
    float mx = red[0]; __syncthreads();
    float e = __expf(v - mx);
    red[tid] = e; __syncthreads();
    for (int o = 128; o > 0; o >>= 1) { if (tid < o) red[tid] += red[tid+o]; __syncthreads(); }
    float p = e / red[0];
    ps[tid] = p;
    __syncthreads();

    if (typeB) {
        outbuf[CP_OFF + ((size_t)b * T_ + (i - 1)) * S_ + tid] = p;
        return;
    }
    if (slice == 0)
        outbuf[AT_OFF + ((size_t)b * T_ + i) * S_ + tid] = p;

    int h = slice * 256 + tid;
    const float* cp = context + (size_t)b * S_ * H_ + h;
    float acc = 0.f;
#pragma unroll 4
    for (int s = 0; s < 256; ++s) acc += ps[s] * cp[(size_t)s * H_];
    g_cvec[b * H_ + h] = acc;
}

// P4: a_out = tanh([cvec|h] @ Wa_out^T) -> d_out. blocks 0..127.
__device__ __forceinline__ void phase_aout(
    float* sh, const float* __restrict__ Wout, float* __restrict__ outbuf,
    int i, const float* __restrict__ hcur)
{
    if (blockIdx.x >= 128) return;
    float* xs = sh;            // [32][68]
    float* ws = sh + 2176;     // [8][68]
    int tid = threadIdx.x, warp = tid >> 5, lane = tid & 31;
    int j0 = blockIdx.x * 8;
    float acc = 0.f;
    for (int ph = 0; ph < 2; ++ph) {
        const float* xb = (ph == 0) ? g_cvec : hcur;
        int coff = (ph == 0) ? 0 : 1024;
        for (int kc = 0; kc < 1024; kc += 64) {
#pragma unroll
            for (int l = 0; l < 2; ++l) {
                int idx = tid + 256 * l, b = idx >> 4, k4 = idx & 15;
                *(float4*)&xs[b * 68 + k4 * 4] = *(const float4*)(xb + b * H_ + kc + k4 * 4);
            }
            if (tid < 128) {
                int lr = tid >> 4, k4 = tid & 15;
                *(float4*)&ws[lr * 68 + k4 * 4] =
                    *(const float4*)(Wout + (size_t)(j0 + lr) * 2048 + coff + kc + k4 * 4);
            }
            __syncthreads();
#pragma unroll
            for (int kk = 0; kk < 16; ++kk) {
                float4 x = *(float4*)&xs[lane * 68 + kk * 4];
                float4 w = *(float4*)&ws[warp * 68 + kk * 4];
                acc += w.x*x.x + w.y*x.y + w.z*x.z + w.w*x.w;
            }
            __syncthreads();
        }
    }
    outbuf[((size_t)lane * T_ + i) * H_ + j0 + warp] = tanhf(acc);
}

// persistent kernel: whole sequential phase, 5 graph nodes total for the run
__global__ __launch_bounds__(256, 2) void k_seq(
    const int* __restrict__ ptv, const int* __restrict__ clen,
    const float* __restrict__ ctx,
    const float* __restrict__ Whh, const float* __restrict__ Wih,
    const float* __restrict__ Wa_out,
    const float* __restrict__ h0, const float* __restrict__ c0,
    float* __restrict__ out)
{
    __shared__ __align__(16) float SH[4352];
    __shared__ int selS[32];

    // P0: init h, c, buf slot 0
    int idx = blockIdx.x * 256 + threadIdx.x;
    if (idx < 32768) {
        g_h[idx] = h0[idx];
        g_c[idx] = c0[idx];
        int b = idx >> 10, j = idx & 1023;
        g_buf[(size_t)b * 257 * 1024 + j] = 0.f;
    }
    gridbar();

    for (int i = 0; i < T_; ++i) {
        const float* hin = g_h + (i & 1) * 32768;
        float*       ho  = g_h + ((i + 1) & 1) * 32768;
        phase_gates(SH, selS, Whh, Wih, ptv, i, hin, ho);
        gridbar();
        phase_scores(clen, out, ho, i, 1, i > 0);
        gridbar();
        phase_cvec(SH, ctx, out, i, 1, i > 0);
        gridbar();
        phase_aout(SH, Wa_out, out, i, ho);
        gridbar();
    }
    // epilogue: copy_scores for step T-1 (attn2 slid by one iteration)
    phase_scores(clen, out, nullptr, T_, 0, 1);
    gridbar();
    phase_cvec(SH, ctx, out, T_, 0, 1);
}

extern "C" void kernel_launch(void* const* d_in, const int* in_sizes, int n_in,
                              void* d_out, int out_size)
{
    (void)in_sizes; (void)n_in; (void)out_size;
    const int*   nt     = (const int*)  d_in[0];
    const int*   prevr  = (const int*)  d_in[1];
    const int*   parr   = (const int*)  d_in[2];
    const int*   ptv    = (const int*)  d_in[3];
    const float* ctx    = (const float*)d_in[4];
    const int*   clen   = (const int*)  d_in[5];
    const float* h0     = (const float*)d_in[6];
    const float* c0     = (const float*)d_in[7];
    const float* nt_emb = (const float*)d_in[8];
    const float* r_emb  = (const float*)d_in[9];
    const float* W_ih   = (const float*)d_in[10];
    const float* W_hh   = (const float*)d_in[11];
    const float* b_ih   = (const float*)d_in[12];
    const float* b_hh   = (const float*)d_in[13];
    const float* Wa_in  = (const float*)d_in[14];
    const float* Wa_out = (const float*)d_in[15];
    const float* Wc_in  = (const float*)d_in[16];
    const float* Wc_out = (const float*)d_in[17];
    float* out = (float*)d_out;
    (void)Wc_out; // only copy probabilities are returned; Wc_out never used

    float *X, *pre, *Ka, *Kc;
    cudaGetSymbolAddress((void**)&X,   g_X);
    cudaGetSymbolAddress((void**)&pre, g_pre);
    cudaGetSymbolAddress((void**)&Ka,  g_Ka);
    cudaGetSymbolAddress((void**)&Kc,  g_Kc);

    k_gather<<<8192, 128>>>(nt, prevr, parr, nt_emb, r_emb);
    sgemm128<1><<<dim3(32, 64), 256>>>(X, IN3D, W_ih, LDIH, pre, 4096, IN3D, b_ih, b_hh);
    sgemm128<0><<<dim3(8, 64), 256>>>(ctx, 1024, Wa_in, 1024, Ka, 1024, 1024, nullptr, nullptr);
    sgemm128<0><<<dim3(8, 64), 256>>>(ctx, 1024, Wc_in, 1024, Kc, 1024, 1024, nullptr, nullptr);
    k_seq<<<GRID_SEQ, 256>>>(ptv, clen, ctx, W_hh, W_ih, Wa_out, h0, c0, out);
}

// round 16
// speedup vs baseline: 1.3048x; 1.3048x over previous
#include <cuda_runtime.h>
#include <cstdint>
#include <cstddef>

#define B_   32
#define T_   256
#define S_   256
#define H_   1024
#define IN3D 1536
#define LDIH 2560
#define AT_OFF 8388608u
#define CP_OFF 10485760u
#define GRID_SEQ 256

// scratch (static device globals; no allocation)
__device__ float g_X  [12582912];   // [8192][1536] row = t*32+b
__device__ float g_pre[33554432];   // [256][32][4096]
__device__ float g_Ka [8388608];    // [32][256][1024]
__device__ float g_Kc [8388608];
__device__ float g_buf[8421376];    // [32][257][1024]
__device__ float g_h  [65536];      // ping-pong [2][32][1024]
__device__ float g_c  [32768];
__device__ float g_cvec[32768];
__device__ float g_sc1[8192];
__device__ float g_sc2[8192];
__device__ unsigned g_barA = 0;
__device__ unsigned g_barGen = 0;

__device__ __forceinline__ float sigm(float x){ return 1.f/(1.f + __expf(-x)); }

// grid-wide barrier (all GRID_SEQ blocks resident)
__device__ __forceinline__ void gridbar()
{
    __syncthreads();
    if (threadIdx.x == 0) {
        volatile unsigned* vg = &g_barGen;
        unsigned gen = *vg;
        __threadfence();
        if (atomicAdd(&g_barA, 1u) == GRID_SEQ - 1u) {
            g_barA = 0u;
            __threadfence();
            *vg = gen + 1u;
        } else {
            while (*vg == gen) __nanosleep(32);
        }
        __threadfence();
    }
    __syncthreads();
}

// ---------------- pre-phase kernels (unchanged from R14, validated) ----------
__global__ void k_gather(const int* __restrict__ nt, const int* __restrict__ pr,
                         const int* __restrict__ par,
                         const float* __restrict__ nt_emb,
                         const float* __restrict__ rule_emb)
{
    int row = blockIdx.x;            // t*32+b
    int t = row >> 5, b = row & 31;
    int tid = threadIdx.x;           // 128
    const float* s0 = nt_emb   + (size_t)nt [b * T_ + t] * 512;
    const float* s1 = rule_emb + (size_t)pr [b * T_ + t] * 512;
    const float* s2 = rule_emb + (size_t)par[b * T_ + t] * 512;
    float4* dst = (float4*)(g_X + (size_t)row * IN3D);
#pragma unroll
    for (int l = 0; l < 3; ++l) {
        int f = tid + 128 * l, seg = f >> 7, off = f & 127;
        const float* sp = (seg == 0) ? s0 : ((seg == 1) ? s1 : s2);
        dst[f] = ((const float4*)sp)[off];
    }
}

template<int BT>
__global__ __launch_bounds__(256) void sgemm128(
    const float* __restrict__ A, int lda,
    const float* __restrict__ Bm, int ldb,
    float* __restrict__ C, int ldc, int K,
    const float* __restrict__ bias1, const float* __restrict__ bias2)
{
    __shared__ __align__(16) float As[16][132];
    __shared__ __align__(16) float Bs[16][132];
    int tid = threadIdx.x;
    int m0 = blockIdx.y * 128, n0 = blockIdx.x * 128;
    int tm = tid >> 4, tn = tid & 15;
    float acc[8][8];
#pragma unroll
    for (int i = 0; i < 8; ++i)
#pragma unroll
        for (int j = 0; j < 8; ++j) acc[i][j] = 0.f;

    for (int kt = 0; kt < K; kt += 16) {
#pragma unroll
        for (int l = 0; l < 2; ++l) {
            int idx = tid + 256 * l, r = idx >> 2, kv = idx & 3;
            float4 v = *(const float4*)(A + (size_t)(m0 + r) * lda + kt + kv * 4);
            As[kv*4+0][r] = v.x; As[kv*4+1][r] = v.y;
            As[kv*4+2][r] = v.z; As[kv*4+3][r] = v.w;
        }
        if (BT) {
#pragma unroll
            for (int l = 0; l < 2; ++l) {
                int idx = tid + 256 * l, r = idx >> 2, kv = idx & 3;
                float4 v = *(const float4*)(Bm + (size_t)(n0 + r) * ldb + kt + kv * 4);
                Bs[kv*4+0][r] = v.x; Bs[kv*4+1][r] = v.y;
                Bs[kv*4+2][r] = v.z; Bs[kv*4+3][r] = v.w;
            }
        } else {
#pragma unroll
            for (int l = 0; l < 2; ++l) {
                int idx = tid + 256 * l, kr = idx >> 5, nv = idx & 31;
                *(float4*)&Bs[kr][nv * 4] =
                    *(const float4*)(Bm + (size_t)(kt + kr) * ldb + n0 + nv * 4);
            }
        }
        __syncthreads();
#pragma unroll
        for (int kk = 0; kk < 16; ++kk) {
            float4 a0 = *(float4*)&As[kk][tm * 8];
            float4 a1 = *(float4*)&As[kk][tm * 8 + 4];
            float4 b0 = *(float4*)&Bs[kk][tn * 8];
            float4 b1 = *(float4*)&Bs[kk][tn * 8 + 4];
            float av[8] = {a0.x,a0.y,a0.z,a0.w,a1.x,a1.y,a1.z,a1.w};
            float bv[8] = {b0.x,b0.y,b0.z,b0.w,b1.x,b1.y,b1.z,b1.w};
#pragma unroll
            for (int i = 0; i < 8; ++i)
#pragma unroll
                for (int j = 0; j < 8; ++j) acc[i][j] += av[i] * bv[j];
        }
        __syncthreads();
    }
#pragma unroll
    for (int i = 0; i < 8; ++i) {
        int m = m0 + tm * 8 + i;
#pragma unroll
        for (int j = 0; j < 8; ++j) {
            int n = n0 + tn * 8 + j;
            float v = acc[i][j];
            if (bias1) v += bias1[n] + bias2[n];
            C[(size_t)m * ldc + n] = v;
        }
    }
}

// ---------------- persistent sequential kernel phases ----------------

// gates body (blocks 0..127): reg-prefetch double-buffered GEMM + LSTM + scatter
__device__ __forceinline__ void gates_body(
    float* sh, int* selS,
    const float* __restrict__ Whh, const float* __restrict__ Wih,
    const int* __restrict__ parent_t, int i,
    const float* __restrict__ hin, float* __restrict__ hout)
{
    float* xs = sh;             // [32][68]
    float* ws = sh + 2176;      // [32][68]
    int tid = threadIdx.x, warp = tid >> 5, lane = tid & 31;
    int j0 = blockIdx.x * 8;
    if (tid < 32) {
        int pidx = parent_t[tid * T_ + i];
        selS[tid] = (pidx < i) ? (pidx + 1) : 0;
    }
    __syncthreads();
    float a0 = 0.f, a1 = 0.f, a2 = 0.f, a3 = 0.f;
    int bA = tid >> 4,        kA = tid & 15;          // load slot A (l=0)
    int bB = (tid + 256) >> 4, kB = tid & 15;         // load slot B (l=1)
    int growA = ((bA >> 3) << 10) + j0 + (bA & 7);    // lr==bA for weights
    int growB = ((bB >> 3) << 10) + j0 + (bB & 7);

    float4 x0, x1, w0, w1, nx0, nx1, nw0, nw1;

#define GLOADC(c, rx0, rx1, rw0, rw1) do {                                     \
    int ph = (c) >> 4, kc = ((c) & 15) * 64;                                   \
    const float* Wb = ph ? Wih : Whh;                                          \
    int ldw = ph ? LDIH : 1024;                                                \
    int coff = ph ? IN3D : 0;                                                  \
    const float* xpA = ph ? (g_buf + ((size_t)bA * 257 + selS[bA]) * 1024)     \
                          : (hin + bA * H_);                                   \
    const float* xpB = ph ? (g_buf + ((size_t)bB * 257 + selS[bB]) * 1024)     \
                          : (hin + bB * H_);                                   \
    rx0 = *(const float4*)(xpA + kc + kA * 4);                                 \
    rx1 = *(const float4*)(xpB + kc + kB * 4);                                 \
    rw0 = *(const float4*)(Wb + (size_t)growA * ldw + coff + kc + kA * 4);     \
    rw1 = *(const float4*)(Wb + (size_t)growB * ldw + coff + kc + kB * 4);     \
} while (0)

#define GSTS(rx0, rx1, rw0, rw1) do {                                          \
    *(float4*)&xs[bA * 68 + kA * 4] = rx0;                                     \
    *(float4*)&xs[bB * 68 + kB * 4] = rx1;                                     \
    *(float4*)&ws[bA * 68 + kA * 4] = rw0;                                     \
    *(float4*)&ws[bB * 68 + kB * 4] = rw1;                                     \
} while (0)

    GLOADC(0, x0, x1, w0, w1);
    GSTS(x0, x1, w0, w1);
    __syncthreads();
    for (int c = 0; c < 32; ++c) {
        if (c < 31) GLOADC(c + 1, nx0, nx1, nw0, nw1);
#pragma unroll
        for (int kk = 0; kk < 16; ++kk) {
            float4 x  = *(float4*)&xs[lane * 68 + kk * 4];
            float4 q0 = *(float4*)&ws[warp * 68 + kk * 4];
            float4 q1 = *(float4*)&ws[(8 + warp) * 68 + kk * 4];
            float4 q2 = *(float4*)&ws[(16 + warp) * 68 + kk * 4];
            float4 q3 = *(float4*)&ws[(24 + warp) * 68 + kk * 4];
            a0 += q0.x*x.x + q0.y*x.y + q0.z*x.z + q0.w*x.w;
            a1 += q1.x*x.x + q1.y*x.y + q1.z*x.z + q1.w*x.w;
            a2 += q2.x*x.x + q2.y*x.y + q2.z*x.z + q2.w*x.w;
            a3 += q3.x*x.x + q3.y*x.y + q3.z*x.z + q3.w*x.w;
        }
        __syncthreads();
        if (c < 31) { GSTS(nx0, nx1, nw0, nw1); __syncthreads(); }
    }
    int b = lane, j = j0 + warp;
    size_t pb = ((size_t)i * 32 + b) * 4096;
    float gi = a0 + g_pre[pb + j];
    float gf = a1 + g_pre[pb + 1024 + j];
    float gg = a2 + g_pre[pb + 2048 + j];
    float go = a3 + g_pre[pb + 3072 + j];
    float cn = sigm(gf) * g_c[b * H_ + j] + sigm(gi) * tanhf(gg);
    float hn = sigm(go) * tanhf(cn);
    g_c[b * H_ + j] = cn;
    hout[b * H_ + j] = hn;
    g_buf[((size_t)b * 257 + i + 1) * 1024 + j] = hn;
#undef GLOADC
#undef GSTS
}

// aout body (blocks 128..255): a_out(step) = tanh([cvec|h] @ Wa_out^T) -> d_out
__device__ __forceinline__ void aout_body(
    float* sh, const float* __restrict__ Wout, float* __restrict__ outbuf,
    int step, const float* __restrict__ hcur)
{
    float* xs = sh;            // [32][68]
    float* ws = sh + 2176;     // [8][68]
    int tid = threadIdx.x, warp = tid >> 5, lane = tid & 31;
    int j0 = (blockIdx.x - 128) * 8;
    float acc = 0.f;
    int bA = tid >> 4,         kA = tid & 15;
    int bB = (tid + 256) >> 4, kB = tid & 15;
    int lw = tid >> 4;         // weight row 0..15 (only tid<128 -> 0..7)
    float4 x0, x1, w0, nx0, nx1, nw0;

#define ALOADC(c, rx0, rx1, rw0) do {                                          \
    int ph = (c) >> 4, kc = ((c) & 15) * 64;                                   \
    const float* xb = ph ? hcur : g_cvec;                                      \
    int coff = ph ? 1024 : 0;                                                  \
    rx0 = *(const float4*)(xb + bA * H_ + kc + kA * 4);                        \
    rx1 = *(const float4*)(xb + bB * H_ + kc + kB * 4);                        \
    if (tid < 128)                                                             \
        rw0 = *(const float4*)(Wout + (size_t)(j0 + lw) * 2048 + coff + kc + kA * 4); \
} while (0)

#define ASTS(rx0, rx1, rw0) do {                                               \
    *(float4*)&xs[bA * 68 + kA * 4] = rx0;                                     \
    *(float4*)&xs[bB * 68 + kB * 4] = rx1;                                     \
    if (tid < 128) *(float4*)&ws[lw * 68 + kA * 4] = rw0;                      \
} while (0)

    ALOADC(0, x0, x1, w0);
    ASTS(x0, x1, w0);
    __syncthreads();
    for (int c = 0; c < 32; ++c) {
        if (c < 31) ALOADC(c + 1, nx0, nx1, nw0);
#pragma unroll
        for (int kk = 0; kk < 16; ++kk) {
            float4 x = *(float4*)&xs[lane * 68 + kk * 4];
            float4 w = *(float4*)&ws[warp * 68 + kk * 4];
            acc += w.x*x.x + w.y*x.y + w.z*x.z + w.w*x.w;
        }
        __syncthreads();
        if (c < 31) { ASTS(nx0, nx1, nw0); __syncthreads(); }
    }
    outbuf[((size_t)lane * T_ + step) * H_ + j0 + warp] = tanhf(acc);
#undef ALOADC
#undef ASTS
}

// scores: 512 warp-units on 256 blocks; q in registers.
// units 0..255: sc1 = h(i).Ka ; 256..511: sc2 = aout(i-1).Kc
__device__ __forceinline__ void phase_scores(
    const int* __restrict__ clen, const float* __restrict__ outbuf,
    const float* __restrict__ hcur, int i, int do1, int do2)
{
    int tid = threadIdx.x, warp = tid >> 5, lane = tid & 31;
    int unit = blockIdx.x * 2 + (warp >> 2);
    int second = (unit >= 256);
    if (second ? !do2 : !do1) return;
    int sub = unit & 255, b = sub >> 3, s0 = (sub & 7) * 32;
    int wIn = warp & 3;

    const float* q;  const float* Km;  float* outp;
    if (!second) { q = hcur + b * H_;                            Km = g_Ka; outp = g_sc1; }
    else         { q = outbuf + ((size_t)b * T_ + (i - 1)) * H_; Km = g_Kc; outp = g_sc2; }
    float4 qv[8];
#pragma unroll
    for (int u = 0; u < 8; ++u) qv[u] = *(const float4*)(q + lane * 4 + u * 128);
    int len = clen[b];
#pragma unroll
    for (int m = 0; m < 8; ++m) {
        int s = s0 + wIn * 8 + m;
        const float* kr = Km + ((size_t)b * S_ + s) * H_;
        float a = 0.f;
#pragma unroll
        for (int u = 0; u < 8; ++u) {
            float4 kv = *(const float4*)(kr + lane * 4 + u * 128);
            a += kv.x*qv[u].x + kv.y*qv[u].y + kv.z*qv[u].z + kv.w*qv[u].w;
        }
#pragma unroll
        for (int o = 16; o > 0; o >>= 1) a += __shfl_xor_sync(0xffffffffu, a, o);
        if (lane == 0) outp[b * S_ + s] = (s < len) ? a : -1e30f;
    }
}

// softmax + cvec slices + score outputs.
// blocks 0..127: (b, hslice) from sc1; 128..159: sc2 -> copy_scores step i-1
__device__ __forceinline__ void phase_cvec(
    float* sh, const float* __restrict__ context, float* __restrict__ outbuf,
    int i, int doA, int doB)
{
    float* ps  = sh;
    float* red = sh + 256;
    int bid = blockIdx.x, tid = threadIdx.x;
    if (bid >= 160) return;
    int typeB = (bid >= 128);
    if (typeB ? !doB : !doA) return;
    int b, slice = 0;
    const float* sc;
    if (!typeB) { b = bid >> 2; slice = bid & 3; sc = g_sc1 + b * S_; }
    else        { b = bid - 128;                 sc = g_sc2 + b * S_; }

    float v = sc[tid];
    red[tid] = v; __syncthreads();
    for (int o = 128; o > 0; o >>= 1) { if (tid < o) red[tid] = fmaxf(red[tid], red[tid+o]); __syncthreads(); }
    float mx = red[0]; __syncthreads();
    float e = __expf(v - mx);
    red[tid] = e; __syncthreads();
    for (int o = 128; o > 0; o >>= 1) { if (tid < o) red[tid] += red[tid+o]; __syncthreads(); }
    float p = e / red[0];
    ps[tid] = p;
    __syncthreads();

    if (typeB) {
        outbuf[CP_OFF + ((size_t)b * T_ + (i - 1)) * S_ + tid] = p;
        return;
    }
    if (slice == 0)
        outbuf[AT_OFF + ((size_t)b * T_ + i) * S_ + tid] = p;

    int h = slice * 256 + tid;
    const float* cp = context + (size_t)b * S_ * H_ + h;
    float acc = 0.f;
#pragma unroll 4
    for (int s = 0; s < 256; ++s) acc += ps[s] * cp[(size_t)s * H_];
    g_cvec[b * H_ + h] = acc;
}

// persistent kernel: whole sequential phase
__global__ __launch_bounds__(256, 2) void k_seq(
    const int* __restrict__ ptv, const int* __restrict__ clen,
    const float* __restrict__ ctx,
    const float* __restrict__ Whh, const float* __restrict__ Wih,
    const float* __restrict__ Wa_out,
    const float* __restrict__ h0, const float* __restrict__ c0,
    float* __restrict__ out)
{
    __shared__ __align__(16) float SH[4352];
    __shared__ int selS[32];

    // init h, c, buf slot 0
    int idx = blockIdx.x * 256 + threadIdx.x;
    if (idx < 32768) {
        g_h[idx] = h0[idx];
        g_c[idx] = c0[idx];
        int b = idx >> 10, j = idx & 1023;
        g_buf[(size_t)b * 257 * 1024 + j] = 0.f;
    }
    gridbar();

    for (int i = 0; i < T_; ++i) {
        const float* hin = g_h + (i & 1) * 32768;       // h(i-1)
        float*       ho  = g_h + ((i + 1) & 1) * 32768; // h(i)
        // merged: gates(i) on blocks 0..127  ||  aout(i-1) on blocks 128..255
        if (blockIdx.x < 128)
            gates_body(SH, selS, Whh, Wih, ptv, i, hin, ho);
        else if (i > 0)
            aout_body(SH, Wa_out, out, i - 1, hin);
        gridbar();
        phase_scores(clen, out, ho, i, 1, i > 0);
        gridbar();
        phase_cvec(SH, ctx, out, i, 1, i > 0);
        gridbar();
    }
    // epilogue: aout(T-1), then its copy_scores
    if (blockIdx.x >= 128)
        aout_body(SH, Wa_out, out, T_ - 1, g_h + (T_ & 1) * 32768);
    gridbar();
    phase_scores(clen, out, nullptr, T_, 0, 1);
    gridbar();
    phase_cvec(SH, ctx, out, T_, 0, 1);
}

extern "C" void kernel_launch(void* const* d_in, const int* in_sizes, int n_in,
                              void* d_out, int out_size)
{
    (void)in_sizes; (void)n_in; (void)out_size;
    const int*   nt     = (const int*)  d_in[0];
    const int*   prevr  = (const int*)  d_in[1];
    const int*   parr   = (const int*)  d_in[2];
    const int*   ptv    = (const int*)  d_in[3];
    const float* ctx    = (const float*)d_in[4];
    const int*   clen   = (const int*)  d_in[5];
    const float* h0     = (const float*)d_in[6];
    const float* c0     = (const float*)d_in[7];
    const float* nt_emb = (const float*)d_in[8];
    const float* r_emb  = (const float*)d_in[9];
    const float* W_ih   = (const float*)d_in[10];
    const float* W_hh   = (const float*)d_in[11];
    const float* b_ih   = (const float*)d_in[12];
    const float* b_hh   = (const float*)d_in[13];
    const float* Wa_in  = (const float*)d_in[14];
    const float* Wa_out = (const float*)d_in[15];
    const float* Wc_in  = (const float*)d_in[16];
    const float* Wc_out = (const float*)d_in[17];
    float* out = (float*)d_out;
    (void)Wc_out;

    float *X, *pre, *Ka, *Kc;
    cudaGetSymbolAddress((void**)&X,   g_X);
    cudaGetSymbolAddress((void**)&pre, g_pre);
    cudaGetSymbolAddress((void**)&Ka,  g_Ka);
    cudaGetSymbolAddress((void**)&Kc,  g_Kc);

    k_gather<<<8192, 128>>>(nt, prevr, parr, nt_emb, r_emb);
    sgemm128<1><<<dim3(32, 64), 256>>>(X, IN3D, W_ih, LDIH, pre, 4096, IN3D, b_ih, b_hh);
    sgemm128<0><<<dim3(8, 64), 256>>>(ctx, 1024, Wa_in, 1024, Ka, 1024, 1024, nullptr, nullptr);
    sgemm128<0><<<dim3(8, 64), 256>>>(ctx, 1024, Wc_in, 1024, Kc, 1024, 1024, nullptr, nullptr);
    k_seq<<<GRID_SEQ, 256>>>(ptv, clen, ctx, W_hh, W_ih, Wa_out, h0, c0, out);
}